// round 11
// baseline (speedup 1.0000x reference)
#include <cuda_runtime.h>
#include <cuda_fp16.h>
#include <cstdint>

#define B_ 8
#define N_ 2048
#define D_ 128
#define KC 64
#define NCH1 32
#define MT 64                 // M tile (j rows per CTA)

#define CHBUF 24576           // stage-1 buffer: A-hi 8K @0, B-hi 16K @8192
#define OFF_B1 8192
#define SM_TILES 1024
#define SMEM_TOTAL (SM_TILES + 3 * CHBUF)   // 74752 B -> 2 CTAs/SM
// stage-2 layout (single buffer at SM_TILES): AH 0 | AL 8192 | BH 16384 | BL 32768
#define S2_AL 8192
#define S2_BH 16384
#define S2_BL 32768

#define SWZ(x) ((x) ^ (((x) >> 3) & 0x70))

// ---- precomputed scratch (no cudaMalloc allowed) ----
__device__ float  g_degree[B_ * N_];
__device__ __half g_CThi[B_ * N_ * N_];   // cost^T [b][j][i] fp16 hi (64 MB)
__device__ __half g_EThi[B_ * D_ * N_];   // E^T  [b][d][i]
__device__ __half g_ENhi[B_ * N_ * D_];   // E    [b][i][d]
__device__ __half g_ENlo[B_ * N_ * D_];
__device__ __half g_Whi[D_ * 2 * D_];     // W    [dout][k]
__device__ __half g_Wlo[D_ * 2 * D_];

__device__ __forceinline__ uint32_t smem_u32(const void* p) {
    uint32_t a;
    asm("{ .reg .u64 t; cvta.to.shared.u64 t, %1; cvt.u32.u64 %0, t; }"
        : "=r"(a) : "l"(p));
    return a;
}
__device__ __forceinline__ void cpasync16(uint32_t dst, const void* src) {
    asm volatile("cp.async.cg.shared.global [%0], [%1], 16;"
                 :: "r"(dst), "l"(src));
}
#define CP_COMMIT() asm volatile("cp.async.commit_group;" ::: "memory")
#define CP_WAIT0()  asm volatile("cp.async.wait_group 0;" ::: "memory")
#define CP_WAIT1()  asm volatile("cp.async.wait_group 1;" ::: "memory")

__device__ __forceinline__ uint32_t cvth2(float x0, float x1) {
    uint32_t H;
    asm("cvt.rn.f16x2.f32 %0, %1, %2;" : "=r"(H) : "f"(x1), "f"(x0));
    return H;
}
__device__ __forceinline__ void split2h(float x0, float x1,
                                        uint32_t& hi, uint32_t& lo) {
    uint32_t H;
    asm("cvt.rn.f16x2.f32 %0, %1, %2;" : "=r"(H) : "f"(x1), "f"(x0));
    float h0, h1;
    asm("{ .reg .f16 a,b; mov.b32 {a,b}, %2; cvt.f32.f16 %0, a; cvt.f32.f16 %1, b; }"
        : "=f"(h0), "=f"(h1) : "r"(H));
    asm("cvt.rn.f16x2.f32 %0, %1, %2;" : "=r"(lo) : "f"(x1 - h1), "f"(x0 - h0));
    hi = H;
}

__device__ __forceinline__ void ldsm4(uint32_t addr, uint32_t r[4]) {
    asm volatile("ldmatrix.sync.aligned.m8n8.x4.shared.b16 {%0,%1,%2,%3}, [%4];"
                 : "=r"(r[0]), "=r"(r[1]), "=r"(r[2]), "=r"(r[3]) : "r"(addr));
}
__device__ __forceinline__ void mma16816(float c[4],
                                         const uint32_t a[4],
                                         uint32_t b0, uint32_t b1) {
    asm volatile(
        "mma.sync.aligned.m16n8k16.row.col.f32.f16.f16.f32 "
        "{%0,%1,%2,%3}, {%4,%5,%6,%7}, {%8,%9}, {%0,%1,%2,%3};"
        : "+f"(c[0]), "+f"(c[1]), "+f"(c[2]), "+f"(c[3])
        : "r"(a[0]), "r"(a[1]), "r"(a[2]), "r"(a[3]), "r"(b0), "r"(b1));
}

// stage-1 slice: acc += Ahi * Bhi   (A rows 0..63 @0, B rows 0..127 @OFF_B1)
__device__ __forceinline__ void mma1p(uint32_t bufR, int ks, int m0, int n0,
                                      int lane, float (&acc)[2][4][4]) {
    const int lr = lane & 15;
    const int kh = (lane >> 4) * 16;
    uint32_t ah[2][4], bh[2][4];
    #pragma unroll
    for (int mt = 0; mt < 2; mt++) {
        int row = m0 + mt * 16 + lr;
        uint32_t off = row * 128 + ((ks * 32 + kh) ^ ((row & 7) << 4));
        ldsm4(bufR + off, ah[mt]);
    }
    #pragma unroll
    for (int nt2 = 0; nt2 < 2; nt2++) {
        int row = n0 + nt2 * 16 + lr;
        uint32_t off = row * 128 + ((ks * 32 + kh) ^ ((row & 7) << 4));
        ldsm4(bufR + OFF_B1 + off, bh[nt2]);
    }
    #pragma unroll
    for (int mt = 0; mt < 2; mt++)
        #pragma unroll
        for (int nt = 0; nt < 4; nt++) {
            int n2 = nt >> 1, sel = nt & 1;
            mma16816(acc[mt][nt], ah[mt], bh[n2][sel], bh[n2][sel + 2]);
        }
}

// stage-2 slice: acc += Ahi*Bhi + Ahi*Blo + Alo*Bhi  (S2 layout)
__device__ __forceinline__ void mma3p(uint32_t bufR, int ks, int m0, int n0,
                                      int lane, float (&acc)[2][4][4]) {
    const int lr = lane & 15;
    const int kh = (lane >> 4) * 16;
    uint32_t ah[2][4], al[2][4], bh[2][4], bl[2][4];
    #pragma unroll
    for (int mt = 0; mt < 2; mt++) {
        int row = m0 + mt * 16 + lr;
        uint32_t off = row * 128 + ((ks * 32 + kh) ^ ((row & 7) << 4));
        ldsm4(bufR + off, ah[mt]);
        ldsm4(bufR + S2_AL + off, al[mt]);
    }
    #pragma unroll
    for (int nt2 = 0; nt2 < 2; nt2++) {
        int row = n0 + nt2 * 16 + lr;
        uint32_t off = row * 128 + ((ks * 32 + kh) ^ ((row & 7) << 4));
        ldsm4(bufR + S2_BH + off, bh[nt2]);
        ldsm4(bufR + S2_BL + off, bl[nt2]);
    }
    #pragma unroll
    for (int ps = 0; ps < 3; ps++)
        #pragma unroll
        for (int mt = 0; mt < 2; mt++)
            #pragma unroll
            for (int nt = 0; nt < 4; nt++) {
                int n2 = nt >> 1, sel = nt & 1;
                const uint32_t* A = (ps == 2) ? al[mt] : ah[mt];
                const uint32_t* Bf = (ps == 1) ? bl[n2] : bh[n2];
                mma16816(acc[mt][nt], A, Bf[sel], Bf[sel + 2]);
            }
}

// ---------------- prep kernels ----------------
// degree[b,j] = sum_i adj[b,j,i]   (one warp per row; measured ~6.4 TB/s)
__global__ void degree_kernel(const float* __restrict__ adj) {
    int warp = (blockIdx.x * blockDim.x + threadIdx.x) >> 5;
    int lane = threadIdx.x & 31;
    if (warp >= B_ * N_) return;
    const float4* row = reinterpret_cast<const float4*>(adj + (size_t)warp * N_);
    float s = 0.f;
    #pragma unroll
    for (int t = 0; t < (N_ / 4) / 32; t++) {
        float4 v = row[t * 32 + lane];
        s += (v.x + v.y) + (v.z + v.w);
    }
    #pragma unroll
    for (int o = 16; o; o >>= 1) s += __shfl_xor_sync(0xffffffffu, s, o);
    if (lane == 0) g_degree[warp] = s;
}

// costT[b][j][i] = fp16(cost[b][i][j])  — 64x64 smem transpose tiles
__global__ void __launch_bounds__(256) prep_costT(const float* __restrict__ cost) {
    __shared__ float s[64][68];
    int b = blockIdx.z;
    int i0 = blockIdx.x * 64, j0 = blockIdx.y * 64;
    int tid = threadIdx.x;
    const float* src = cost + ((size_t)b * N_ + i0) * N_ + j0;
    #pragma unroll
    for (int q = 0; q < 4; q++) {
        int idx = q * 256 + tid;
        int ri = idx >> 4, j4 = idx & 15;
        float4 v = *reinterpret_cast<const float4*>(src + (size_t)ri * N_ + j4 * 4);
        *reinterpret_cast<float4*>(&s[ri][j4 * 4]) = v;
    }
    __syncthreads();
    __half* dst = g_CThi + ((size_t)b * N_ + j0) * N_ + i0;
    #pragma unroll
    for (int q = 0; q < 8; q++) {
        int idx = q * 256 + tid;
        int jr = idx >> 5, c = idx & 31;
        uint32_t h = cvth2(s[2 * c][jr], s[2 * c + 1][jr]);
        *reinterpret_cast<uint32_t*>(dst + (size_t)jr * N_ + 2 * c) = h;
    }
}

__global__ void prep_E(const float* __restrict__ E) {
    __shared__ float s[32][33];
    int b = blockIdx.z;
    int i0 = blockIdx.x * 32, d0 = blockIdx.y * 32;
    int tx = threadIdx.x, ty = threadIdx.y;   // (32, 8)
    #pragma unroll
    for (int q = 0; q < 4; q++) {
        int i = i0 + ty + 8 * q, d = d0 + tx;
        float v = E[((size_t)b * N_ + i) * D_ + d];
        s[ty + 8 * q][tx] = v;
        __half h = __float2half_rn(v);
        __half l = __float2half_rn(v - __half2float(h));
        size_t idx = ((size_t)b * N_ + i) * D_ + d;
        g_ENhi[idx] = h; g_ENlo[idx] = l;
    }
    __syncthreads();
    #pragma unroll
    for (int q = 0; q < 4; q++) {
        int d = d0 + ty + 8 * q, i = i0 + tx;
        size_t idx = ((size_t)b * D_ + d) * N_ + i;
        g_EThi[idx] = __float2half_rn(s[tx][ty + 8 * q]);
    }
}

__global__ void prep_W(const float* __restrict__ W) {
    int i = blockIdx.x * 256 + threadIdx.x;
    float v = W[i];
    __half h = __float2half_rn(v);
    g_Whi[i] = h;
    g_Wlo[i] = __float2half_rn(v - __half2float(h));
}

// ---------------- fused main kernel (M=64, 2 CTAs/SM, all-cp.async) ---------
__global__ void __launch_bounds__(256, 2)
fused(const float* __restrict__ bias, float* __restrict__ out) {
    extern __shared__ char smem[];
    const uint32_t sb = smem_u32(smem);
    float* sDeg = reinterpret_cast<float*>(smem);   // 64 floats, front region

    const int tid = threadIdx.x, w = tid >> 5, l = tid & 31;
    const int wm = w >> 2, wn = w & 3;              // wm 0..1, wn 0..3
    const int m0 = wm * 32, n0 = wn * 32;
    const int b = blockIdx.y, jBase = blockIdx.x * MT;

    const __half* CT  = g_CThi + ((size_t)b * N_ + jBase) * N_;  // [j][i]
    const __half* ETh = g_EThi + (size_t)b * D_ * N_;            // [d][i]

    float acc[2][4][4];
    #pragma unroll
    for (int mt = 0; mt < 2; mt++)
        #pragma unroll
        for (int nt = 0; nt < 4; nt++)
            #pragma unroll
            for (int q = 0; q < 4; q++) acc[mt][nt][q] = 0.f;

    // ---- prologue: chunks 0,1 -> buf0,buf1 ----
    #pragma unroll
    for (int c0 = 0; c0 < 2; c0++) {
        const uint32_t bufW = sb + SM_TILES + c0 * CHBUF;
        const int k0 = c0 * KC;
        #pragma unroll
        for (int q = 0; q < 2; q++) {
            int idx = q * 256 + tid;
            int row = idx >> 3, i8 = idx & 7;
            cpasync16(bufW + SWZ(row * 128 + i8 * 16),
                      CT + (size_t)row * N_ + k0 + i8 * 8);
        }
        #pragma unroll
        for (int q = 0; q < 4; q++) {
            int idx = q * 256 + tid;
            int d = idx >> 3, i8 = idx & 7;
            cpasync16(bufW + OFF_B1 + SWZ(d * 128 + i8 * 16),
                      ETh + (size_t)d * N_ + k0 + i8 * 8);
        }
        CP_COMMIT();
    }
    CP_WAIT1();
    __syncthreads();

    // ================= Stage 1 mainloop =================
    for (int c = 0; c < NCH1; c++) {
        const uint32_t bufR = sb + SM_TILES + (c % 3) * CHBUF;
        if (c + 2 < NCH1) {
            const uint32_t bufW = sb + SM_TILES + ((c + 2) % 3) * CHBUF;
            const int k0 = (c + 2) * KC;
            #pragma unroll
            for (int q = 0; q < 2; q++) {
                int idx = q * 256 + tid;
                int row = idx >> 3, i8 = idx & 7;
                cpasync16(bufW + SWZ(row * 128 + i8 * 16),
                          CT + (size_t)row * N_ + k0 + i8 * 8);
            }
            #pragma unroll
            for (int q = 0; q < 4; q++) {
                int idx = q * 256 + tid;
                int d = idx >> 3, i8 = idx & 7;
                cpasync16(bufW + OFF_B1 + SWZ(d * 128 + i8 * 16),
                          ETh + (size_t)d * N_ + k0 + i8 * 8);
            }
            CP_COMMIT();
        }
        #pragma unroll
        for (int ks = 0; ks < 4; ks++)
            mma1p(bufR, ks, m0, n0, l, acc);
        if (c >= NCH1 - 2) CP_WAIT0(); else CP_WAIT1();
        __syncthreads();
    }

    // ---- degrees -> smem (precomputed by degree_kernel) ----
    if (tid < MT) sDeg[tid] = g_degree[b * N_ + jBase + tid];
    __syncthreads();

    // ========= Stage 2: out = relu([E|SN] @ W^T + b), single-buffered ======
    float acc2[2][4][4];
    #pragma unroll
    for (int mt = 0; mt < 2; mt++)
        #pragma unroll
        for (int nt = 0; nt < 4; nt++)
            #pragma unroll
            for (int q = 0; q < 4; q++) acc2[mt][nt][q] = 0.f;

    const __half* ENh = g_ENhi + (size_t)b * N_ * D_;
    const __half* ENl = g_ENlo + (size_t)b * N_ * D_;
    char* S2c = smem + SM_TILES;
    const uint32_t S2b = sb + SM_TILES;

    #pragma unroll
    for (int cs = 0; cs < 4; cs++) {
        const int s = (cs < 2) ? cs + 2 : cs - 2;   // SN chunks first

        // B2 = W tile [dout 128][64 k] hi+lo
        #pragma unroll
        for (int q = 0; q < 4; q++) {
            int idx = q * 256 + tid;
            int d = idx >> 3, k8 = idx & 7;
            uint32_t off = SWZ(d * 128 + k8 * 16);
            cpasync16(S2b + S2_BH + off, g_Whi + d * 256 + s * 64 + k8 * 8);
            cpasync16(S2b + S2_BL + off, g_Wlo + d * 256 + s * 64 + k8 * 8);
        }
        if (s < 2) {
            // A2 = E rows jBase.., cols 64s..
            #pragma unroll
            for (int q = 0; q < 2; q++) {
                int idx = q * 256 + tid;
                int row = idx >> 3, d8 = idx & 7;
                uint32_t off = SWZ(row * 128 + d8 * 16);
                const size_t srcOff = (size_t)(jBase + row) * D_ + s * 64 + d8 * 8;
                cpasync16(S2b + off, ENh + srcOff);
                cpasync16(S2b + S2_AL + off, ENl + srcOff);
            }
        } else {
            // A2 = SN (hi+lo) from stage-1 accumulators
            if ((wn >> 1) == (s - 2)) {
                #pragma unroll
                for (int mt = 0; mt < 2; mt++) {
                    int r0 = m0 + mt * 16 + (l >> 2);
                    float rd0 = 1.0f / sDeg[r0];
                    float rd1 = 1.0f / sDeg[r0 + 8];
                    #pragma unroll
                    for (int nt = 0; nt < 4; nt++) {
                        int k = (wn & 1) * 32 + nt * 8 + (l & 3) * 2;
                        uint32_t h, lo;
                        split2h(acc[mt][nt][0] * rd0, acc[mt][nt][1] * rd0, h, lo);
                        uint32_t off = SWZ(r0 * 128 + k * 2);
                        *reinterpret_cast<uint32_t*>(S2c + off) = h;
                        *reinterpret_cast<uint32_t*>(S2c + S2_AL + off) = lo;
                        split2h(acc[mt][nt][2] * rd1, acc[mt][nt][3] * rd1, h, lo);
                        off = SWZ((r0 + 8) * 128 + k * 2);
                        *reinterpret_cast<uint32_t*>(S2c + off) = h;
                        *reinterpret_cast<uint32_t*>(S2c + S2_AL + off) = lo;
                    }
                }
            }
        }
        CP_COMMIT();
        CP_WAIT0();
        __syncthreads();
        #pragma unroll
        for (int ks = 0; ks < 4; ks++)
            mma3p(S2b, ks, m0, n0, l, acc2);
        __syncthreads();
    }

    // ---- epilogue: bias + relu + store ----
    #pragma unroll
    for (int mt = 0; mt < 2; mt++)
        #pragma unroll
        for (int nt = 0; nt < 4; nt++) {
            int col = n0 + nt * 8 + (l & 3) * 2;
            float2 bv = *reinterpret_cast<const float2*>(bias + col);
            int r0 = jBase + m0 + mt * 16 + (l >> 2);
            float2 o0, o1;
            o0.x = fmaxf(acc2[mt][nt][0] + bv.x, 0.f);
            o0.y = fmaxf(acc2[mt][nt][1] + bv.y, 0.f);
            o1.x = fmaxf(acc2[mt][nt][2] + bv.x, 0.f);
            o1.y = fmaxf(acc2[mt][nt][3] + bv.y, 0.f);
            *reinterpret_cast<float2*>(
                out + (size_t)b * N_ * D_ + (size_t)r0 * D_ + col) = o0;
            *reinterpret_cast<float2*>(
                out + (size_t)b * N_ * D_ + (size_t)(r0 + 8) * D_ + col) = o1;
        }
}

// ---------------------------------------------------------------------------
extern "C" void kernel_launch(void* const* d_in, const int* in_sizes, int n_in,
                              void* d_out, int out_size) {
    const float* E    = (const float*)d_in[0];
    const float* adj  = (const float*)d_in[1];
    const float* cost = (const float*)d_in[2];
    const float* W    = (const float*)d_in[3];
    const float* bias = (const float*)d_in[4];
    float* out = (float*)d_out;

    {
        dim3 grid(N_ / 32, D_ / 32, B_);
        dim3 blk(32, 8);
        prep_E<<<grid, blk>>>(E);
        prep_W<<<(D_ * 2 * D_) / 256, 256>>>(W);
        degree_kernel<<<(B_ * N_ * 32 + 255) / 256, 256>>>(adj);
        dim3 gridT(N_ / 64, N_ / 64, B_);
        prep_costT<<<gridT, 256>>>(cost);
    }
    cudaFuncSetAttribute(fused, cudaFuncAttributeMaxDynamicSharedMemorySize,
                         SMEM_TOTAL);
    dim3 grid(N_ / MT, B_);
    fused<<<grid, 256, SMEM_TOTAL>>>(bias, out);
}

// round 12
// speedup vs baseline: 1.6101x; 1.6101x over previous
#include <cuda_runtime.h>
#include <cuda_fp16.h>
#include <cstdint>

#define B_ 8
#define N_ 2048
#define D_ 128
#define KC 64
#define NCH1 32
#define MT 64                 // M tile (j rows per CTA)

// ---- stage-1 smem rings ----
#define A32_SZ 17408          // 64 rows x 272B (fp32 cost tile, padded)
#define A16_SZ 8192           // 64 x 128B fp16 (swizzled)
#define B16_SZ 16384          // 128 x 128B fp16 (swizzled)
#define A32_0  1024
#define A16_0  (A32_0 + 2 * A32_SZ)          // 35840
#define B16_0  (A16_0 + 3 * A16_SZ)          // 60416
#define SMEM_TOTAL (B16_0 + 3 * B16_SZ)      // 109568 -> 2 CTAs/SM
// ---- stage-2 layout (reuses smem from offset 1024) ----
#define S2_0   1024
#define S2_AL  8192
#define S2_BH  16384
#define S2_BL  32768

#define SWZ(x) ((x) ^ (((x) >> 3) & 0x70))

// ---- precomputed fp16 (device scratch; no cudaMalloc allowed) ----
__device__ __half g_EThi[B_ * D_ * N_];   // E^T  [b][d][i]   (hi only)
__device__ __half g_ENhi[B_ * N_ * D_];   // E    [b][i][d]
__device__ __half g_ENlo[B_ * N_ * D_];
__device__ __half g_Whi[D_ * 2 * D_];     // W    [dout][k]
__device__ __half g_Wlo[D_ * 2 * D_];

__device__ __forceinline__ uint32_t smem_u32(const void* p) {
    uint32_t a;
    asm("{ .reg .u64 t; cvta.to.shared.u64 t, %1; cvt.u32.u64 %0, t; }"
        : "=r"(a) : "l"(p));
    return a;
}
__device__ __forceinline__ void cpasync16(uint32_t dst, const void* src) {
    asm volatile("cp.async.cg.shared.global [%0], [%1], 16;"
                 :: "r"(dst), "l"(src));
}
#define CP_COMMIT() asm volatile("cp.async.commit_group;" ::: "memory")
#define CP_WAIT0()  asm volatile("cp.async.wait_group 0;" ::: "memory")
#define CP_WAIT1()  asm volatile("cp.async.wait_group 1;" ::: "memory")

__device__ __forceinline__ uint32_t cvth2(float x0, float x1) {
    uint32_t H;
    asm("cvt.rn.f16x2.f32 %0, %1, %2;" : "=r"(H) : "f"(x1), "f"(x0));
    return H;
}
__device__ __forceinline__ void split2h(float x0, float x1,
                                        uint32_t& hi, uint32_t& lo) {
    uint32_t H;
    asm("cvt.rn.f16x2.f32 %0, %1, %2;" : "=r"(H) : "f"(x1), "f"(x0));
    float h0, h1;
    asm("{ .reg .f16 a,b; mov.b32 {a,b}, %2; cvt.f32.f16 %0, a; cvt.f32.f16 %1, b; }"
        : "=f"(h0), "=f"(h1) : "r"(H));
    asm("cvt.rn.f16x2.f32 %0, %1, %2;" : "=r"(lo) : "f"(x1 - h1), "f"(x0 - h0));
    hi = H;
}

__device__ __forceinline__ void ldsm4(uint32_t addr, uint32_t r[4]) {
    asm volatile("ldmatrix.sync.aligned.m8n8.x4.shared.b16 {%0,%1,%2,%3}, [%4];"
                 : "=r"(r[0]), "=r"(r[1]), "=r"(r[2]), "=r"(r[3]) : "r"(addr));
}
__device__ __forceinline__ void ldsm4t(uint32_t addr, uint32_t r[4]) {
    asm volatile("ldmatrix.sync.aligned.m8n8.x4.trans.shared.b16 {%0,%1,%2,%3}, [%4];"
                 : "=r"(r[0]), "=r"(r[1]), "=r"(r[2]), "=r"(r[3]) : "r"(addr));
}
__device__ __forceinline__ void mma16816(float c[4],
                                         const uint32_t a[4],
                                         uint32_t b0, uint32_t b1) {
    asm volatile(
        "mma.sync.aligned.m16n8k16.row.col.f32.f16.f16.f32 "
        "{%0,%1,%2,%3}, {%4,%5,%6,%7}, {%8,%9}, {%0,%1,%2,%3};"
        : "+f"(c[0]), "+f"(c[1]), "+f"(c[2]), "+f"(c[3])
        : "r"(a[0]), "r"(a[1]), "r"(a[2]), "r"(a[3]), "r"(b0), "r"(b1));
}

// stage-1 slice: acc += A * B.  A fragments come from the NATURAL-layout
// fp16 cost tile S[i=64][j=64] via ldmatrix.trans (A[m=j][k=i] = S[k][m]^T).
__device__ __forceinline__ void mma1pT(uint32_t bufA, uint32_t bufB, int ks,
                                       int m0, int n0, int lane,
                                       float (&acc)[2][4][4]) {
    const int lr = lane & 15;
    const int kh = (lane >> 4) * 16;
    const int g8 = lane >> 3;            // 0..3
    const int lr8 = lane & 7;
    uint32_t ah[2][4], bh[2][4];
    #pragma unroll
    for (int mt = 0; mt < 2; mt++) {
        int srow = ks * 16 + (g8 >> 1) * 8 + lr8;          // i
        int scolb = (m0 + mt * 16 + (g8 & 1) * 8) * 2;     // j bytes
        uint32_t off = srow * 128 + (scolb ^ ((srow & 7) << 4));
        ldsm4t(bufA + off, ah[mt]);
    }
    #pragma unroll
    for (int nt2 = 0; nt2 < 2; nt2++) {
        int row = n0 + nt2 * 16 + lr;
        uint32_t off = row * 128 + ((ks * 32 + kh) ^ ((row & 7) << 4));
        ldsm4(bufB + off, bh[nt2]);
    }
    #pragma unroll
    for (int mt = 0; mt < 2; mt++)
        #pragma unroll
        for (int nt = 0; nt < 4; nt++) {
            int n2 = nt >> 1, sel = nt & 1;
            mma16816(acc[mt][nt], ah[mt], bh[n2][sel], bh[n2][sel + 2]);
        }
}

// stage-2 slice: acc += Ahi*Bhi + Ahi*Blo + Alo*Bhi  (S2 layout, normal ldsm)
__device__ __forceinline__ void mma3p(uint32_t bufR, int ks, int m0, int n0,
                                      int lane, float (&acc)[2][4][4]) {
    const int lr = lane & 15;
    const int kh = (lane >> 4) * 16;
    uint32_t ah[2][4], al[2][4], bh[2][4], bl[2][4];
    #pragma unroll
    for (int mt = 0; mt < 2; mt++) {
        int row = m0 + mt * 16 + lr;
        uint32_t off = row * 128 + ((ks * 32 + kh) ^ ((row & 7) << 4));
        ldsm4(bufR + off, ah[mt]);
        ldsm4(bufR + S2_AL + off, al[mt]);
    }
    #pragma unroll
    for (int nt2 = 0; nt2 < 2; nt2++) {
        int row = n0 + nt2 * 16 + lr;
        uint32_t off = row * 128 + ((ks * 32 + kh) ^ ((row & 7) << 4));
        ldsm4(bufR + S2_BH + off, bh[nt2]);
        ldsm4(bufR + S2_BL + off, bl[nt2]);
    }
    #pragma unroll
    for (int ps = 0; ps < 3; ps++)
        #pragma unroll
        for (int mt = 0; mt < 2; mt++)
            #pragma unroll
            for (int nt = 0; nt < 4; nt++) {
                int n2 = nt >> 1, sel = nt & 1;
                const uint32_t* A = (ps == 2) ? al[mt] : ah[mt];
                const uint32_t* Bf = (ps == 1) ? bl[n2] : bh[n2];
                mma16816(acc[mt][nt], A, Bf[sel], Bf[sel + 2]);
            }
}

// ---------------- prep kernels ----------------
__global__ void prep_E(const float* __restrict__ E) {
    __shared__ float s[32][33];
    int b = blockIdx.z;
    int i0 = blockIdx.x * 32, d0 = blockIdx.y * 32;
    int tx = threadIdx.x, ty = threadIdx.y;   // (32, 8)
    #pragma unroll
    for (int q = 0; q < 4; q++) {
        int i = i0 + ty + 8 * q, d = d0 + tx;
        float v = E[((size_t)b * N_ + i) * D_ + d];
        s[ty + 8 * q][tx] = v;
        __half h = __float2half_rn(v);
        __half l = __float2half_rn(v - __half2float(h));
        size_t idx = ((size_t)b * N_ + i) * D_ + d;
        g_ENhi[idx] = h; g_ENlo[idx] = l;
    }
    __syncthreads();
    #pragma unroll
    for (int q = 0; q < 4; q++) {
        int d = d0 + ty + 8 * q, i = i0 + tx;
        size_t idx = ((size_t)b * D_ + d) * N_ + i;
        g_EThi[idx] = __float2half_rn(s[tx][ty + 8 * q]);
    }
}

__global__ void prep_W(const float* __restrict__ W) {
    int i = blockIdx.x * 256 + threadIdx.x;
    float v = W[i];
    __half h = __float2half_rn(v);
    g_Whi[i] = h;
    g_Wlo[i] = __float2half_rn(v - __half2float(h));
}

// ---------------- fused main kernel (M=64, 2 CTAs/SM) ----------------
__global__ void __launch_bounds__(256, 2)
fused(const float* __restrict__ cost, const float* __restrict__ adj,
      const float* __restrict__ bias, float* __restrict__ out) {
    extern __shared__ char smem[];
    const uint32_t sb = smem_u32(smem);
    float* sDeg = reinterpret_cast<float*>(smem);   // 64 floats @0

    const int tid = threadIdx.x, w = tid >> 5, l = tid & 31;
    const int wm = w >> 2, wn = w & 3;              // wm 0..1, wn 0..3
    const int m0 = wm * 32, n0 = wn * 32;
    const int b = blockIdx.y, jBase = blockIdx.x * MT;

    const float* Cb = cost + (size_t)b * N_ * N_ + jBase;        // [i][jBase+j]
    const float* Ab = adj + (size_t)b * N_ * N_ + (size_t)jBase * N_;
    const __half* ETh = g_EThi + (size_t)b * D_ * N_;            // [d][i]

    // convert-pass thread mapping (conflict-free LDS.128)
    const int iC = tid & 63, jgC = tid >> 6;
    // adj loader mapping (validated rounds 5-10)
    const int dRow = w * 8 + (l >> 4);
    const int dCol = (l & 15) * 4;

    float acc[2][4][4];
    #pragma unroll
    for (int mt = 0; mt < 2; mt++)
        #pragma unroll
        for (int nt = 0; nt < 4; nt++)
            #pragma unroll
            for (int q = 0; q < 4; q++) acc[mt][nt][q] = 0.f;
    float dacc[4] = {0.f, 0.f, 0.f, 0.f};
    float4 pd[4];

    // ---- prologue: cp.async chunks 0,1 (A fp32 + B fp16); adj chunk 0 ----
    #pragma unroll
    for (int c0 = 0; c0 < 2; c0++) {
        const int k0 = c0 * KC;
        uint32_t a32d = sb + A32_0 + c0 * A32_SZ;
        #pragma unroll
        for (int q = 0; q < 4; q++) {
            int idx = q * 256 + tid;
            int i = idx >> 4, jf = idx & 15;
            cpasync16(a32d + i * 272 + jf * 16,
                      Cb + (size_t)(k0 + i) * N_ + jf * 4);
        }
        uint32_t bd = sb + B16_0 + c0 * B16_SZ;
        #pragma unroll
        for (int q = 0; q < 4; q++) {
            int idx = q * 256 + tid;
            int d = idx >> 3, i8 = idx & 7;
            cpasync16(bd + SWZ(d * 128 + i8 * 16),
                      ETh + (size_t)d * N_ + k0 + i8 * 8);
        }
        CP_COMMIT();
    }
    #pragma unroll
    for (int g = 0; g < 4; g++)
        pd[g] = *reinterpret_cast<const float4*>(
            Ab + (size_t)(dRow + 2 * g) * N_ + dCol);

    // ================= Stage 1 mainloop =================
    for (int c = 0; c < NCH1; c++) {
        if (c >= NCH1 - 2) CP_WAIT0(); else CP_WAIT1();
        __syncthreads();                                    // chunk c in smem

        // convert A fp32 (slot c&1) -> fp16 swizzled (slot c%3)
        {
            const char* a32 = smem + A32_0 + (c & 1) * A32_SZ + iC * 272 + jgC * 64;
            char* a16 = smem + A16_0 + (c % 3) * A16_SZ;
            #pragma unroll
            for (int e = 0; e < 4; e++) {
                float4 v = *reinterpret_cast<const float4*>(a32 + e * 16);
                uint32_t h0 = cvth2(v.x, v.y);
                uint32_t h1 = cvth2(v.z, v.w);
                uint32_t off = iC * 128 +
                    (((jgC * 16 + e * 4) * 2) ^ ((iC & 7) << 4));
                *reinterpret_cast<uint2*>(a16 + off) = make_uint2(h0, h1);
            }
        }
        __syncthreads();                                    // A16 ready; A32 free

        if (c + 2 < NCH1) {      // prefetch chunk c+2
            const int k0 = (c + 2) * KC;
            uint32_t a32d = sb + A32_0 + (c & 1) * A32_SZ;  // (c+2)&1 == c&1
            #pragma unroll
            for (int q = 0; q < 4; q++) {
                int idx = q * 256 + tid;
                int i = idx >> 4, jf = idx & 15;
                cpasync16(a32d + i * 272 + jf * 16,
                          Cb + (size_t)(k0 + i) * N_ + jf * 4);
            }
            uint32_t bd = sb + B16_0 + ((c + 2) % 3) * B16_SZ;
            #pragma unroll
            for (int q = 0; q < 4; q++) {
                int idx = q * 256 + tid;
                int d = idx >> 3, i8 = idx & 7;
                cpasync16(bd + SWZ(d * 128 + i8 * 16),
                          ETh + (size_t)d * N_ + k0 + i8 * 8);
            }
            CP_COMMIT();
        }

        // degree: accumulate chunk c, load chunk c+1
        #pragma unroll
        for (int g = 0; g < 4; g++)
            dacc[g] += (pd[g].x + pd[g].y) + (pd[g].z + pd[g].w);
        if (c + 1 < NCH1) {
            const int k1 = (c + 1) * KC;
            #pragma unroll
            for (int g = 0; g < 4; g++)
                pd[g] = *reinterpret_cast<const float4*>(
                    Ab + (size_t)(dRow + 2 * g) * N_ + k1 + dCol);
        }

        const uint32_t bufA = sb + A16_0 + (c % 3) * A16_SZ;
        const uint32_t bufB = sb + B16_0 + (c % 3) * B16_SZ;
        #pragma unroll
        for (int ks = 0; ks < 4; ks++)
            mma1pT(bufA, bufB, ks, m0, n0, l, acc);
    }
    __syncthreads();

    // ---- degrees -> smem ----
    #pragma unroll
    for (int t = 0; t < 4; t++) {
        float s = dacc[t];
        s += __shfl_xor_sync(~0u, s, 1);
        s += __shfl_xor_sync(~0u, s, 2);
        s += __shfl_xor_sync(~0u, s, 4);
        s += __shfl_xor_sync(~0u, s, 8);
        if ((l & 15) == 0) sDeg[dRow + 2 * t] = s;
    }
    __syncthreads();

    // ========= Stage 2: out = relu([E|SN] @ W^T + b), single-buffered ======
    float acc2[2][4][4];
    #pragma unroll
    for (int mt = 0; mt < 2; mt++)
        #pragma unroll
        for (int nt = 0; nt < 4; nt++)
            #pragma unroll
            for (int q = 0; q < 4; q++) acc2[mt][nt][q] = 0.f;

    const __half* ENh = g_ENhi + (size_t)b * N_ * D_;
    const __half* ENl = g_ENlo + (size_t)b * N_ * D_;
    char* S2c = smem + S2_0;
    const uint32_t S2b = sb + S2_0;

    #pragma unroll
    for (int cs = 0; cs < 4; cs++) {
        const int s = (cs < 2) ? cs + 2 : cs - 2;   // SN chunks first

        #pragma unroll
        for (int q = 0; q < 4; q++) {
            int idx = q * 256 + tid;
            int d = idx >> 3, k8 = idx & 7;
            uint32_t off = SWZ(d * 128 + k8 * 16);
            cpasync16(S2b + S2_BH + off, g_Whi + d * 256 + s * 64 + k8 * 8);
            cpasync16(S2b + S2_BL + off, g_Wlo + d * 256 + s * 64 + k8 * 8);
        }
        if (s < 2) {
            #pragma unroll
            for (int q = 0; q < 2; q++) {
                int idx = q * 256 + tid;
                int row = idx >> 3, d8 = idx & 7;
                uint32_t off = SWZ(row * 128 + d8 * 16);
                const size_t srcOff = (size_t)(jBase + row) * D_ + s * 64 + d8 * 8;
                cpasync16(S2b + off, ENh + srcOff);
                cpasync16(S2b + S2_AL + off, ENl + srcOff);
            }
        } else {
            if ((wn >> 1) == (s - 2)) {
                #pragma unroll
                for (int mt = 0; mt < 2; mt++) {
                    int r0 = m0 + mt * 16 + (l >> 2);
                    float rd0 = 1.0f / sDeg[r0];
                    float rd1 = 1.0f / sDeg[r0 + 8];
                    #pragma unroll
                    for (int nt = 0; nt < 4; nt++) {
                        int k = (wn & 1) * 32 + nt * 8 + (l & 3) * 2;
                        uint32_t h, lo;
                        split2h(acc[mt][nt][0] * rd0, acc[mt][nt][1] * rd0, h, lo);
                        uint32_t off = SWZ(r0 * 128 + k * 2);
                        *reinterpret_cast<uint32_t*>(S2c + off) = h;
                        *reinterpret_cast<uint32_t*>(S2c + S2_AL + off) = lo;
                        split2h(acc[mt][nt][2] * rd1, acc[mt][nt][3] * rd1, h, lo);
                        off = SWZ((r0 + 8) * 128 + k * 2);
                        *reinterpret_cast<uint32_t*>(S2c + off) = h;
                        *reinterpret_cast<uint32_t*>(S2c + S2_AL + off) = lo;
                    }
                }
            }
        }
        CP_COMMIT();
        CP_WAIT0();
        __syncthreads();
        #pragma unroll
        for (int ks = 0; ks < 4; ks++)
            mma3p(S2b, ks, m0, n0, l, acc2);
        __syncthreads();
    }

    // ---- epilogue: bias + relu + store ----
    #pragma unroll
    for (int mt = 0; mt < 2; mt++)
        #pragma unroll
        for (int nt = 0; nt < 4; nt++) {
            int col = n0 + nt * 8 + (l & 3) * 2;
            float2 bv = *reinterpret_cast<const float2*>(bias + col);
            int r0 = jBase + m0 + mt * 16 + (l >> 2);
            float2 o0, o1;
            o0.x = fmaxf(acc2[mt][nt][0] + bv.x, 0.f);
            o0.y = fmaxf(acc2[mt][nt][1] + bv.y, 0.f);
            o1.x = fmaxf(acc2[mt][nt][2] + bv.x, 0.f);
            o1.y = fmaxf(acc2[mt][nt][3] + bv.y, 0.f);
            *reinterpret_cast<float2*>(
                out + (size_t)b * N_ * D_ + (size_t)r0 * D_ + col) = o0;
            *reinterpret_cast<float2*>(
                out + (size_t)b * N_ * D_ + (size_t)(r0 + 8) * D_ + col) = o1;
        }
}

// ---------------------------------------------------------------------------
extern "C" void kernel_launch(void* const* d_in, const int* in_sizes, int n_in,
                              void* d_out, int out_size) {
    const float* E    = (const float*)d_in[0];
    const float* adj  = (const float*)d_in[1];
    const float* cost = (const float*)d_in[2];
    const float* W    = (const float*)d_in[3];
    const float* bias = (const float*)d_in[4];
    float* out = (float*)d_out;

    {
        dim3 grid(N_ / 32, D_ / 32, B_);
        dim3 blk(32, 8);
        prep_E<<<grid, blk>>>(E);
        prep_W<<<(D_ * 2 * D_) / 256, 256>>>(W);
    }
    cudaFuncSetAttribute(fused, cudaFuncAttributeMaxDynamicSharedMemorySize,
                         SMEM_TOTAL);
    dim3 grid(N_ / MT, B_);
    fused<<<grid, 256, SMEM_TOTAL>>>(cost, adj, bias, out);
}

// round 13
// speedup vs baseline: 1.6494x; 1.0244x over previous
#include <cuda_runtime.h>
#include <cuda_fp16.h>
#include <cstdint>

#define B_ 8
#define N_ 2048
#define D_ 128
#define KC 64
#define NCH1 32
#define MT 64                 // M tile (j rows per CTA)

// ---- stage-1 smem rings ----
#define A32_SZ 16384          // 64 rows x 256B fp32, 16B-block swizzled
#define A16_SZ 8192           // 64 x 128B fp16 (swizzled), single buffer
#define B16_SZ 16384          // 128 x 128B fp16 (swizzled)
#define A32_0  1024
#define A16_0  (A32_0 + 3 * A32_SZ)          // 50176
#define B16_0  (A16_0 + A16_SZ)              // 58368
#define SMEM_TOTAL (B16_0 + 3 * B16_SZ)      // 107520 -> 2 CTAs/SM
// ---- stage-2 layout (reuses smem from offset 1024; top 50176 < total) ----
#define S2_0   1024
#define S2_AL  8192
#define S2_BH  16384
#define S2_BL  32768

#define SWZ(x) ((x) ^ (((x) >> 3) & 0x70))
// fp32 A tile: row pitch 256B, 16B-block swizzle
#define SWZ32(i, col16) ((i) * 256 + (((col16) * 16) ^ (((i) & 15) << 4)))

// ---- precomputed fp16 (device scratch; no cudaMalloc allowed) ----
__device__ __half g_EThi[B_ * D_ * N_];   // E^T  [b][d][i]   (hi only)
__device__ __half g_ENhi[B_ * N_ * D_];   // E    [b][i][d]
__device__ __half g_ENlo[B_ * N_ * D_];
__device__ __half g_Whi[D_ * 2 * D_];     // W    [dout][k]
__device__ __half g_Wlo[D_ * 2 * D_];

__device__ __forceinline__ uint32_t smem_u32(const void* p) {
    uint32_t a;
    asm("{ .reg .u64 t; cvta.to.shared.u64 t, %1; cvt.u32.u64 %0, t; }"
        : "=r"(a) : "l"(p));
    return a;
}
__device__ __forceinline__ void cpasync16(uint32_t dst, const void* src) {
    asm volatile("cp.async.cg.shared.global [%0], [%1], 16;"
                 :: "r"(dst), "l"(src));
}
#define CP_COMMIT() asm volatile("cp.async.commit_group;" ::: "memory")
#define CP_WAIT0()  asm volatile("cp.async.wait_group 0;" ::: "memory")
#define CP_WAIT1()  asm volatile("cp.async.wait_group 1;" ::: "memory")
#define CP_WAIT2()  asm volatile("cp.async.wait_group 2;" ::: "memory")

__device__ __forceinline__ uint32_t cvth2(float x0, float x1) {
    uint32_t H;
    asm("cvt.rn.f16x2.f32 %0, %1, %2;" : "=r"(H) : "f"(x1), "f"(x0));
    return H;
}
__device__ __forceinline__ void split2h(float x0, float x1,
                                        uint32_t& hi, uint32_t& lo) {
    uint32_t H;
    asm("cvt.rn.f16x2.f32 %0, %1, %2;" : "=r"(H) : "f"(x1), "f"(x0));
    float h0, h1;
    asm("{ .reg .f16 a,b; mov.b32 {a,b}, %2; cvt.f32.f16 %0, a; cvt.f32.f16 %1, b; }"
        : "=f"(h0), "=f"(h1) : "r"(H));
    asm("cvt.rn.f16x2.f32 %0, %1, %2;" : "=r"(lo) : "f"(x1 - h1), "f"(x0 - h0));
    hi = H;
}

__device__ __forceinline__ void ldsm4(uint32_t addr, uint32_t r[4]) {
    asm volatile("ldmatrix.sync.aligned.m8n8.x4.shared.b16 {%0,%1,%2,%3}, [%4];"
                 : "=r"(r[0]), "=r"(r[1]), "=r"(r[2]), "=r"(r[3]) : "r"(addr));
}
__device__ __forceinline__ void ldsm4t(uint32_t addr, uint32_t r[4]) {
    asm volatile("ldmatrix.sync.aligned.m8n8.x4.trans.shared.b16 {%0,%1,%2,%3}, [%4];"
                 : "=r"(r[0]), "=r"(r[1]), "=r"(r[2]), "=r"(r[3]) : "r"(addr));
}
__device__ __forceinline__ void mma16816(float c[4],
                                         const uint32_t a[4],
                                         uint32_t b0, uint32_t b1) {
    asm volatile(
        "mma.sync.aligned.m16n8k16.row.col.f32.f16.f16.f32 "
        "{%0,%1,%2,%3}, {%4,%5,%6,%7}, {%8,%9}, {%0,%1,%2,%3};"
        : "+f"(c[0]), "+f"(c[1]), "+f"(c[2]), "+f"(c[3])
        : "r"(a[0]), "r"(a[1]), "r"(a[2]), "r"(a[3]), "r"(b0), "r"(b1));
}

// stage-1 slice: acc += A * B.  A fragments from natural-layout fp16 cost
// tile S[i=64][j=64] via ldmatrix.trans.
__device__ __forceinline__ void mma1pT(uint32_t bufA, uint32_t bufB, int ks,
                                       int m0, int n0, int lane,
                                       float (&acc)[2][4][4]) {
    const int lr = lane & 15;
    const int kh = (lane >> 4) * 16;
    const int g8 = lane >> 3;            // 0..3
    const int lr8 = lane & 7;
    uint32_t ah[2][4], bh[2][4];
    #pragma unroll
    for (int mt = 0; mt < 2; mt++) {
        int srow = ks * 16 + (g8 >> 1) * 8 + lr8;          // i
        int scolb = (m0 + mt * 16 + (g8 & 1) * 8) * 2;     // j bytes
        uint32_t off = srow * 128 + (scolb ^ ((srow & 7) << 4));
        ldsm4t(bufA + off, ah[mt]);
    }
    #pragma unroll
    for (int nt2 = 0; nt2 < 2; nt2++) {
        int row = n0 + nt2 * 16 + lr;
        uint32_t off = row * 128 + ((ks * 32 + kh) ^ ((row & 7) << 4));
        ldsm4(bufB + off, bh[nt2]);
    }
    #pragma unroll
    for (int mt = 0; mt < 2; mt++)
        #pragma unroll
        for (int nt = 0; nt < 4; nt++) {
            int n2 = nt >> 1, sel = nt & 1;
            mma16816(acc[mt][nt], ah[mt], bh[n2][sel], bh[n2][sel + 2]);
        }
}

// stage-2 slice: acc += Ahi*Bhi + Ahi*Blo + Alo*Bhi
__device__ __forceinline__ void mma3p(uint32_t bufR, int ks, int m0, int n0,
                                      int lane, float (&acc)[2][4][4]) {
    const int lr = lane & 15;
    const int kh = (lane >> 4) * 16;
    uint32_t ah[2][4], al[2][4], bh[2][4], bl[2][4];
    #pragma unroll
    for (int mt = 0; mt < 2; mt++) {
        int row = m0 + mt * 16 + lr;
        uint32_t off = row * 128 + ((ks * 32 + kh) ^ ((row & 7) << 4));
        ldsm4(bufR + off, ah[mt]);
        ldsm4(bufR + S2_AL + off, al[mt]);
    }
    #pragma unroll
    for (int nt2 = 0; nt2 < 2; nt2++) {
        int row = n0 + nt2 * 16 + lr;
        uint32_t off = row * 128 + ((ks * 32 + kh) ^ ((row & 7) << 4));
        ldsm4(bufR + S2_BH + off, bh[nt2]);
        ldsm4(bufR + S2_BL + off, bl[nt2]);
    }
    #pragma unroll
    for (int ps = 0; ps < 3; ps++)
        #pragma unroll
        for (int mt = 0; mt < 2; mt++)
            #pragma unroll
            for (int nt = 0; nt < 4; nt++) {
                int n2 = nt >> 1, sel = nt & 1;
                const uint32_t* A = (ps == 2) ? al[mt] : ah[mt];
                const uint32_t* Bf = (ps == 1) ? bl[n2] : bh[n2];
                mma16816(acc[mt][nt], A, Bf[sel], Bf[sel + 2]);
            }
}

// ---------------- prep kernels ----------------
__global__ void prep_E(const float* __restrict__ E) {
    __shared__ float s[32][33];
    int b = blockIdx.z;
    int i0 = blockIdx.x * 32, d0 = blockIdx.y * 32;
    int tx = threadIdx.x, ty = threadIdx.y;   // (32, 8)
    #pragma unroll
    for (int q = 0; q < 4; q++) {
        int i = i0 + ty + 8 * q, d = d0 + tx;
        float v = E[((size_t)b * N_ + i) * D_ + d];
        s[ty + 8 * q][tx] = v;
        __half h = __float2half_rn(v);
        __half l = __float2half_rn(v - __half2float(h));
        size_t idx = ((size_t)b * N_ + i) * D_ + d;
        g_ENhi[idx] = h; g_ENlo[idx] = l;
    }
    __syncthreads();
    #pragma unroll
    for (int q = 0; q < 4; q++) {
        int d = d0 + ty + 8 * q, i = i0 + tx;
        size_t idx = ((size_t)b * D_ + d) * N_ + i;
        g_EThi[idx] = __float2half_rn(s[tx][ty + 8 * q]);
    }
}

__global__ void prep_W(const float* __restrict__ W) {
    int i = blockIdx.x * 256 + threadIdx.x;
    float v = W[i];
    __half h = __float2half_rn(v);
    g_Whi[i] = h;
    g_Wlo[i] = __float2half_rn(v - __half2float(h));
}

// ---------------- fused main kernel (M=64, 2 CTAs/SM, depth-3 ring) --------
__global__ void __launch_bounds__(256, 2)
fused(const float* __restrict__ cost, const float* __restrict__ adj,
      const float* __restrict__ bias, float* __restrict__ out) {
    extern __shared__ char smem[];
    const uint32_t sb = smem_u32(smem);
    float* sDeg = reinterpret_cast<float*>(smem);   // 64 floats @0

    const int tid = threadIdx.x, w = tid >> 5, l = tid & 31;
    const int wm = w >> 2, wn = w & 3;              // wm 0..1, wn 0..3
    const int m0 = wm * 32, n0 = wn * 32;
    const int b = blockIdx.y, jBase = blockIdx.x * MT;

    const float* Cb = cost + (size_t)b * N_ * N_ + jBase;        // [i][jBase+j]
    const float* Ab = adj + (size_t)b * N_ * N_ + (size_t)jBase * N_;
    const __half* ETh = g_EThi + (size_t)b * D_ * N_;            // [d][i]

    // loader thread mappings
    const int iA = tid >> 2, jfA = (tid & 3);       // A32: 4 x (i, 4 cols of 16B)
    const int iC = tid & 63, jgC = tid >> 6;        // convert pass
    const int dRow = w * 8 + (l >> 4);              // adj
    const int dCol = (l & 15) * 4;

    float acc[2][4][4];
    #pragma unroll
    for (int mt = 0; mt < 2; mt++)
        #pragma unroll
        for (int nt = 0; nt < 4; nt++)
            #pragma unroll
            for (int q = 0; q < 4; q++) acc[mt][nt][q] = 0.f;
    float dacc[4] = {0.f, 0.f, 0.f, 0.f};
    float4 pd[4];

    // ---- prologue: groups G0={A32_0,B16_0}, G1={A32_1,B16_1}, G2={A32_2} --
    #pragma unroll
    for (int c0 = 0; c0 < 2; c0++) {
        const int k0 = c0 * KC;
        uint32_t a32d = sb + A32_0 + c0 * A32_SZ;
        #pragma unroll
        for (int q = 0; q < 4; q++) {
            int idx = q * 256 + tid;
            int i = idx >> 4, jf = idx & 15;
            cpasync16(a32d + SWZ32(i, jf), Cb + (size_t)(k0 + i) * N_ + jf * 4);
        }
        uint32_t bd = sb + B16_0 + c0 * B16_SZ;
        #pragma unroll
        for (int q = 0; q < 4; q++) {
            int idx = q * 256 + tid;
            int d = idx >> 3, i8 = idx & 7;
            cpasync16(bd + SWZ(d * 128 + i8 * 16),
                      ETh + (size_t)d * N_ + k0 + i8 * 8);
        }
        CP_COMMIT();
    }
    {
        uint32_t a32d = sb + A32_0 + 2 * A32_SZ;
        #pragma unroll
        for (int q = 0; q < 4; q++) {
            int idx = q * 256 + tid;
            int i = idx >> 4, jf = idx & 15;
            cpasync16(a32d + SWZ32(i, jf),
                      Cb + (size_t)(2 * KC + i) * N_ + jf * 4);
        }
        CP_COMMIT();
    }
    #pragma unroll
    for (int g = 0; g < 4; g++)
        pd[g] = *reinterpret_cast<const float4*>(
            Ab + (size_t)(dRow + 2 * g) * N_ + dCol);

    // ================= Stage 1 mainloop =================
    // iter c: wait A32(c)+B16(c); convert; commit {A32(c+3), B16(c+2)}; MMA.
    for (int c = 0; c < NCH1; c++) {
        if (c < 2) CP_WAIT2(); else CP_WAIT1();
        __syncthreads();                                   // chunk c ready

        // convert A fp32 (slot c%3) -> fp16 swizzled (single A16 buffer)
        {
            const char* a32 = smem + A32_0 + (c % 3) * A32_SZ;
            char* a16 = smem + A16_0;
            #pragma unroll
            for (int e = 0; e < 4; e++) {
                float4 v = *reinterpret_cast<const float4*>(
                    a32 + SWZ32(iC, jgC * 4 + e));
                uint32_t h0 = cvth2(v.x, v.y);
                uint32_t h1 = cvth2(v.z, v.w);
                uint32_t off = iC * 128 +
                    (((jgC * 16 + e * 4) * 2) ^ ((iC & 7) << 4));
                *reinterpret_cast<uint2*>(a16 + off) = make_uint2(h0, h1);
            }
        }
        __syncthreads();                                   // A16 ready; A32 free

        if (c + 3 < NCH1) {      // A32 chunk c+3 -> slot (c+3)%3 == c%3
            const int k0 = (c + 3) * KC;
            uint32_t a32d = sb + A32_0 + (c % 3) * A32_SZ;
            #pragma unroll
            for (int q = 0; q < 4; q++) {
                int idx = q * 256 + tid;
                int i = idx >> 4, jf = idx & 15;
                cpasync16(a32d + SWZ32(i, jf),
                          Cb + (size_t)(k0 + i) * N_ + jf * 4);
            }
        }
        if (c + 2 < NCH1) {      // B16 chunk c+2 -> slot (c+2)%3
            const int k0 = (c + 2) * KC;
            uint32_t bd = sb + B16_0 + ((c + 2) % 3) * B16_SZ;
            #pragma unroll
            for (int q = 0; q < 4; q++) {
                int idx = q * 256 + tid;
                int d = idx >> 3, i8 = idx & 7;
                cpasync16(bd + SWZ(d * 128 + i8 * 16),
                          ETh + (size_t)d * N_ + k0 + i8 * 8);
            }
        }
        CP_COMMIT();             // (possibly empty at tail — keeps counts uniform)

        // degree: accumulate chunk c, load chunk c+1
        #pragma unroll
        for (int g = 0; g < 4; g++)
            dacc[g] += (pd[g].x + pd[g].y) + (pd[g].z + pd[g].w);
        if (c + 1 < NCH1) {
            const int k1 = (c + 1) * KC;
            #pragma unroll
            for (int g = 0; g < 4; g++)
                pd[g] = *reinterpret_cast<const float4*>(
                    Ab + (size_t)(dRow + 2 * g) * N_ + k1 + dCol);
        }

        const uint32_t bufA = sb + A16_0;
        const uint32_t bufB = sb + B16_0 + (c % 3) * B16_SZ;
        #pragma unroll
        for (int ks = 0; ks < 4; ks++)
            mma1pT(bufA, bufB, ks, m0, n0, l, acc);
    }
    __syncthreads();

    // ---- degrees -> smem ----
    #pragma unroll
    for (int t = 0; t < 4; t++) {
        float s = dacc[t];
        s += __shfl_xor_sync(~0u, s, 1);
        s += __shfl_xor_sync(~0u, s, 2);
        s += __shfl_xor_sync(~0u, s, 4);
        s += __shfl_xor_sync(~0u, s, 8);
        if ((l & 15) == 0) sDeg[dRow + 2 * t] = s;
    }
    __syncthreads();

    // ========= Stage 2: out = relu([E|SN] @ W^T + b), single-buffered ======
    float acc2[2][4][4];
    #pragma unroll
    for (int mt = 0; mt < 2; mt++)
        #pragma unroll
        for (int nt = 0; nt < 4; nt++)
            #pragma unroll
            for (int q = 0; q < 4; q++) acc2[mt][nt][q] = 0.f;

    const __half* ENh = g_ENhi + (size_t)b * N_ * D_;
    const __half* ENl = g_ENlo + (size_t)b * N_ * D_;
    char* S2c = smem + S2_0;
    const uint32_t S2b = sb + S2_0;

    #pragma unroll
    for (int cs = 0; cs < 4; cs++) {
        const int s = (cs < 2) ? cs + 2 : cs - 2;   // SN chunks first

        #pragma unroll
        for (int q = 0; q < 4; q++) {
            int idx = q * 256 + tid;
            int d = idx >> 3, k8 = idx & 7;
            uint32_t off = SWZ(d * 128 + k8 * 16);
            cpasync16(S2b + S2_BH + off, g_Whi + d * 256 + s * 64 + k8 * 8);
            cpasync16(S2b + S2_BL + off, g_Wlo + d * 256 + s * 64 + k8 * 8);
        }
        if (s < 2) {
            #pragma unroll
            for (int q = 0; q < 2; q++) {
                int idx = q * 256 + tid;
                int row = idx >> 3, d8 = idx & 7;
                uint32_t off = SWZ(row * 128 + d8 * 16);
                const size_t srcOff = (size_t)(jBase + row) * D_ + s * 64 + d8 * 8;
                cpasync16(S2b + off, ENh + srcOff);
                cpasync16(S2b + S2_AL + off, ENl + srcOff);
            }
        } else {
            if ((wn >> 1) == (s - 2)) {
                #pragma unroll
                for (int mt = 0; mt < 2; mt++) {
                    int r0 = m0 + mt * 16 + (l >> 2);
                    float rd0 = 1.0f / sDeg[r0];
                    float rd1 = 1.0f / sDeg[r0 + 8];
                    #pragma unroll
                    for (int nt = 0; nt < 4; nt++) {
                        int k = (wn & 1) * 32 + nt * 8 + (l & 3) * 2;
                        uint32_t h, lo;
                        split2h(acc[mt][nt][0] * rd0, acc[mt][nt][1] * rd0, h, lo);
                        uint32_t off = SWZ(r0 * 128 + k * 2);
                        *reinterpret_cast<uint32_t*>(S2c + off) = h;
                        *reinterpret_cast<uint32_t*>(S2c + S2_AL + off) = lo;
                        split2h(acc[mt][nt][2] * rd1, acc[mt][nt][3] * rd1, h, lo);
                        off = SWZ((r0 + 8) * 128 + k * 2);
                        *reinterpret_cast<uint32_t*>(S2c + off) = h;
                        *reinterpret_cast<uint32_t*>(S2c + S2_AL + off) = lo;
                    }
                }
            }
        }
        CP_COMMIT();
        CP_WAIT0();
        __syncthreads();
        #pragma unroll
        for (int ks = 0; ks < 4; ks++)
            mma3p(S2b, ks, m0, n0, l, acc2);
        __syncthreads();
    }

    // ---- epilogue: bias + relu + store ----
    #pragma unroll
    for (int mt = 0; mt < 2; mt++)
        #pragma unroll
        for (int nt = 0; nt < 4; nt++) {
            int col = n0 + nt * 8 + (l & 3) * 2;
            float2 bv = *reinterpret_cast<const float2*>(bias + col);
            int r0 = jBase + m0 + mt * 16 + (l >> 2);
            float2 o0, o1;
            o0.x = fmaxf(acc2[mt][nt][0] + bv.x, 0.f);
            o0.y = fmaxf(acc2[mt][nt][1] + bv.y, 0.f);
            o1.x = fmaxf(acc2[mt][nt][2] + bv.x, 0.f);
            o1.y = fmaxf(acc2[mt][nt][3] + bv.y, 0.f);
            *reinterpret_cast<float2*>(
                out + (size_t)b * N_ * D_ + (size_t)r0 * D_ + col) = o0;
            *reinterpret_cast<float2*>(
                out + (size_t)b * N_ * D_ + (size_t)(r0 + 8) * D_ + col) = o1;
        }
}

// ---------------------------------------------------------------------------
extern "C" void kernel_launch(void* const* d_in, const int* in_sizes, int n_in,
                              void* d_out, int out_size) {
    const float* E    = (const float*)d_in[0];
    const float* adj  = (const float*)d_in[1];
    const float* cost = (const float*)d_in[2];
    const float* W    = (const float*)d_in[3];
    const float* bias = (const float*)d_in[4];
    float* out = (float*)d_out;

    {
        dim3 grid(N_ / 32, D_ / 32, B_);
        dim3 blk(32, 8);
        prep_E<<<grid, blk>>>(E);
        prep_W<<<(D_ * 2 * D_) / 256, 256>>>(W);
    }
    cudaFuncSetAttribute(fused, cudaFuncAttributeMaxDynamicSharedMemorySize,
                         SMEM_TOTAL);
    dim3 grid(N_ / MT, B_);
    fused<<<grid, 256, SMEM_TOTAL>>>(cost, adj, bias, out);
}